// round 11
// baseline (speedup 1.0000x reference)
#include <cuda_runtime.h>
#include <cuda_bf16.h>
#include <cstdint>

// Problem constants
#define Bn 512
#define Sn 512
#define Dn 512
#define LN_EPS 1e-5f

// Scratch (no allocations allowed)
__device__ float g_info[Bn * Dn];      // embeded_info [B, D]  (1 MB)
__device__ int   g_cnt[Bn];            // per-row sentinel counts
__device__ int   g_rank[Bn * Sn];      // intra-row sentinel rank (sparse: only at sentinels)

// ---------------------------------------------------------------------------
// Kernel 1: embeded_info = concat(LN(scores)@Ws+bs, oya_e, dora_e, hrs@Wh+bh) @ W_info + b_info
// Tiling: block = 8 batch rows x 128 output cols, blockDim = 128.
// grid = (Dn/128, Bn/8) = (4, 64) = 256 blocks.
// Blocks with blockIdx.x == 0 additionally compute per-row sentinel counts and
// intra-row ranks for their 8 batch rows (ballot/popc, order-preserving).
// ---------------------------------------------------------------------------
__global__ __launch_bounds__(128) void kernel_info(
    const float* __restrict__ scores,      // [B,4]
    const int*   __restrict__ oya,         // [B]
    const int*   __restrict__ dora,        // [B,5]
    const float* __restrict__ hrs,         // [B,2]
    const int*   __restrict__ action,      // [B,S] (for fused count)
    const float* __restrict__ oya_table,   // [4,16]
    const float* __restrict__ dora_table,  // [38,64]
    const float* __restrict__ ln_gamma,    // [4]
    const float* __restrict__ ln_beta,     // [4]
    const float* __restrict__ W_scores,    // [4,32]
    const float* __restrict__ b_scores,    // [32]
    const float* __restrict__ W_hrs,       // [2,16]
    const float* __restrict__ b_hrs,       // [16]
    const float* __restrict__ W_info,      // [384,512]
    const float* __restrict__ b_info)      // [512]
{
    __shared__ float csh[8 * 384];   // concat rows, 12 KB

    const int tid = threadIdx.x;
    const int b0  = blockIdx.y * 8;

    // Build the 8 concat rows (384 wide) cooperatively.
    for (int r = 0; r < 8; ++r) {
        const int b = b0 + r;
        float s0 = scores[b * 4 + 0], s1 = scores[b * 4 + 1];
        float s2 = scores[b * 4 + 2], s3 = scores[b * 4 + 3];
        float mu  = 0.25f * (s0 + s1 + s2 + s3);
        float d0 = s0 - mu, d1 = s1 - mu, d2 = s2 - mu, d3 = s3 - mu;
        float var = 0.25f * (d0 * d0 + d1 * d1 + d2 * d2 + d3 * d3);
        float rstd = rsqrtf(var + LN_EPS);
        float n0 = d0 * rstd * ln_gamma[0] + ln_beta[0];
        float n1 = d1 * rstd * ln_gamma[1] + ln_beta[1];
        float n2 = d2 * rstd * ln_gamma[2] + ln_beta[2];
        float n3 = d3 * rstd * ln_gamma[3] + ln_beta[3];

        for (int kk = tid; kk < 384; kk += 128) {
            float v;
            if (kk < 32) {
                v = b_scores[kk]
                  + n0 * W_scores[0 * 32 + kk] + n1 * W_scores[1 * 32 + kk]
                  + n2 * W_scores[2 * 32 + kk] + n3 * W_scores[3 * 32 + kk];
            } else if (kk < 48) {
                v = oya_table[oya[b] * 16 + (kk - 32)];
            } else if (kk < 368) {
                int j = (kk - 48) >> 6;
                int c = (kk - 48) & 63;
                v = dora_table[dora[b * 5 + j] * 64 + c];
            } else {
                int c = kk - 368;
                v = b_hrs[c] + hrs[b * 2 + 0] * W_hrs[0 * 16 + c]
                             + hrs[b * 2 + 1] * W_hrs[1 * 16 + c];
            }
            csh[r * 384 + kk] = v;
        }
    }
    __syncthreads();

    // GEMM: each thread owns one output column c, accumulates 8 rows.
    const int c = blockIdx.x * 128 + tid;
    float acc[8];
#pragma unroll
    for (int r = 0; r < 8; ++r) acc[r] = 0.f;

    const float4* csh4 = reinterpret_cast<const float4*>(csh);  // row stride = 96 float4
#pragma unroll 4
    for (int k4 = 0; k4 < 96; ++k4) {
        float cf[8][4];
#pragma unroll
        for (int r = 0; r < 8; ++r) {
            float4 q = csh4[r * 96 + k4];
            cf[r][0] = q.x; cf[r][1] = q.y; cf[r][2] = q.z; cf[r][3] = q.w;
        }
#pragma unroll
        for (int kk = 0; kk < 4; ++kk) {
            float w = W_info[(k4 * 4 + kk) * Dn + c];
#pragma unroll
            for (int r = 0; r < 8; ++r) acc[r] += cf[r][kk] * w;
        }
    }

    float bi = b_info[c];
#pragma unroll
    for (int r = 0; r < 8; ++r)
        g_info[(b0 + r) * Dn + c] = acc[r] + bi;

    // Fused sentinel count + rank for this block's 8 rows (only x==0 blocks).
    // Warp w handles rows r = w and r = w + 4 sequentially; lanes sweep 32
    // consecutive s per ballot iteration, so rank order == s order.
    if (blockIdx.x == 0) {
        const int wid  = tid >> 5;
        const int lane = tid & 31;
        const unsigned lmask = (1u << lane) - 1u;
#pragma unroll
        for (int rr = 0; rr < 2; ++rr) {
            const int b = b0 + wid + rr * 4;
            int base = 0;
            for (int it = 0; it < Sn / 32; ++it) {
                int s = it * 32 + lane;
                int a = action[b * Sn + s];
                unsigned bal = __ballot_sync(0xffffffffu, a == 224);
                if (a == 224)
                    g_rank[b * Sn + s] = base + __popc(bal & lmask);
                base += __popc(bal);
            }
            if (lane == 0) g_cnt[b] = base;
        }
    }
}

// ---------------------------------------------------------------------------
// Kernel 2: single-pass gather + sentinel substitution (the 537 MB write).
// For each position: a != 224 -> action_table[a]; a == 224 -> g_info[occ]
// with occ = clip(prefix(b) + rank). The row prefix is computed on the fly,
// warp-cooperatively (<=16 coalesced g_cnt loads + shuffle reduce), only in
// the warp-uniform sentinel branch (~1/512 of rows) -- this removes the
// separate scan kernel and its launch gap entirely.
// 8 independent float4 per thread; streaming stores keep action_table hot.
// ---------------------------------------------------------------------------
#define MAIN_TPB 256
#define MAIN_VPT 8
__global__ __launch_bounds__(MAIN_TPB) void kernel_main(
    const int*   __restrict__ action,       // [B*S]
    const float* __restrict__ action_table, // [225, 512]
    float*       __restrict__ out)          // [B*S*D]
{
    const int stride = gridDim.x * MAIN_TPB;           // = n4 / MAIN_VPT
    const int idx  = blockIdx.x * MAIN_TPB + threadIdx.x;
    const int lane = threadIdx.x & 31;
    const float4* tbl4  = reinterpret_cast<const float4*>(action_table);
    const float4* info4 = reinterpret_cast<const float4*>(g_info);
    float4*       out4  = reinterpret_cast<float4*>(out);

    int    id[MAIN_VPT];
    float4 v[MAIN_VPT];
#pragma unroll
    for (int i = 0; i < MAIN_VPT; ++i) {
        id[i] = idx + i * stride;
        int bs = id[i] >> 7;          // /128 float4 per (b,s); warp-uniform
        int d4 = id[i] & 127;
        int a  = __ldg(&action[bs]);
        const float4* src;
        if (a == 224) {
            // Warp-uniform branch: all 32 lanes share this bs.
            int b = bs >> 9;
            int p = 0;
            for (int j = lane; j < b; j += 32) p += g_cnt[j];
#pragma unroll
            for (int off = 16; off > 0; off >>= 1)
                p += __shfl_xor_sync(0xffffffffu, p, off);
            int occ = p + __ldg(&g_rank[bs]);
            occ = occ < (Bn - 1) ? occ : (Bn - 1);   // clip (occ >= 0 always)
            src = info4 + occ * 128;
        } else {
            src = tbl4 + a * 128;
        }
        v[i] = __ldg(&src[d4]);
    }
#pragma unroll
    for (int i = 0; i < MAIN_VPT; ++i)
        __stcs(&out4[id[i]], v[i]);
}

// ---------------------------------------------------------------------------
// Launch
// Input order (metadata): scores, oya, dora, honba_riichi_sticks, action, mask,
//   action_table, oya_table, dora_table, ln_gamma, ln_beta, W_scores, b_scores,
//   W_hrs, b_hrs, W_info, b_info
// ---------------------------------------------------------------------------
extern "C" void kernel_launch(void* const* d_in, const int* in_sizes, int n_in,
                              void* d_out, int out_size)
{
    const float* scores       = (const float*)d_in[0];
    const int*   oya          = (const int*)  d_in[1];
    const int*   dora         = (const int*)  d_in[2];
    const float* hrs          = (const float*)d_in[3];
    const int*   action       = (const int*)  d_in[4];
    /* mask d_in[5] unused */
    const float* action_table = (const float*)d_in[6];
    const float* oya_table    = (const float*)d_in[7];
    const float* dora_table   = (const float*)d_in[8];
    const float* ln_gamma     = (const float*)d_in[9];
    const float* ln_beta      = (const float*)d_in[10];
    const float* W_scores     = (const float*)d_in[11];
    const float* b_scores     = (const float*)d_in[12];
    const float* W_hrs        = (const float*)d_in[13];
    const float* b_hrs        = (const float*)d_in[14];
    const float* W_info       = (const float*)d_in[15];
    const float* b_info       = (const float*)d_in[16];
    float* out = (float*)d_out;

    dim3 gi(Dn / 128, Bn / 8);
    kernel_info<<<gi, 128>>>(scores, oya, dora, hrs, action,
                             oya_table, dora_table,
                             ln_gamma, ln_beta, W_scores, b_scores,
                             W_hrs, b_hrs, W_info, b_info);

    const int n4   = Bn * Sn * (Dn / 4);
    const int grid = n4 / (MAIN_TPB * MAIN_VPT);   // 16384
    kernel_main<<<grid, MAIN_TPB>>>(action, action_table, out);
}

// round 17
// speedup vs baseline: 1.1907x; 1.1907x over previous
#include <cuda_runtime.h>
#include <cuda_bf16.h>
#include <cstdint>

// Problem constants
#define Bn 512
#define Sn 512
#define Dn 512
#define LN_EPS 1e-5f
#define TBL_ROWS 737            // 225 action rows + 512 info rows
#define INFO_BASE 225

// Scratch (no allocations allowed)
__device__ float g_table[TBL_ROWS * Dn];  // unified gather table (1.51 MB)
__device__ int   g_cnt[Bn];               // per-row sentinel counts
__device__ int   g_rank[Bn * Sn];         // intra-row sentinel rank (sparse)
__device__ int   g_row[Bn * Sn];          // final per-position table row index

// ---------------------------------------------------------------------------
// Kernel 1: info GEMM -> g_table rows 225..736; action_table copy -> rows
// 0..224 (blocks x=1..3); sentinel count+rank (blocks x=0).
// grid = (4, 64), block = 128.
// ---------------------------------------------------------------------------
__global__ __launch_bounds__(128) void kernel_info(
    const float* __restrict__ scores,      // [B,4]
    const int*   __restrict__ oya,         // [B]
    const int*   __restrict__ dora,        // [B,5]
    const float* __restrict__ hrs,         // [B,2]
    const int*   __restrict__ action,      // [B,S]
    const float* __restrict__ action_table,// [225,512]
    const float* __restrict__ oya_table,   // [4,16]
    const float* __restrict__ dora_table,  // [38,64]
    const float* __restrict__ ln_gamma,    // [4]
    const float* __restrict__ ln_beta,     // [4]
    const float* __restrict__ W_scores,    // [4,32]
    const float* __restrict__ b_scores,    // [32]
    const float* __restrict__ W_hrs,       // [2,16]
    const float* __restrict__ b_hrs,       // [16]
    const float* __restrict__ W_info,      // [384,512]
    const float* __restrict__ b_info)      // [512]
{
    __shared__ float csh[8 * 384];   // concat rows, 12 KB

    const int tid = threadIdx.x;
    const int b0  = blockIdx.y * 8;

    // Build the 8 concat rows (384 wide) cooperatively.
    for (int r = 0; r < 8; ++r) {
        const int b = b0 + r;
        float s0 = scores[b * 4 + 0], s1 = scores[b * 4 + 1];
        float s2 = scores[b * 4 + 2], s3 = scores[b * 4 + 3];
        float mu  = 0.25f * (s0 + s1 + s2 + s3);
        float d0 = s0 - mu, d1 = s1 - mu, d2 = s2 - mu, d3 = s3 - mu;
        float var = 0.25f * (d0 * d0 + d1 * d1 + d2 * d2 + d3 * d3);
        float rstd = rsqrtf(var + LN_EPS);
        float n0 = d0 * rstd * ln_gamma[0] + ln_beta[0];
        float n1 = d1 * rstd * ln_gamma[1] + ln_beta[1];
        float n2 = d2 * rstd * ln_gamma[2] + ln_beta[2];
        float n3 = d3 * rstd * ln_gamma[3] + ln_beta[3];

        for (int kk = tid; kk < 384; kk += 128) {
            float v;
            if (kk < 32) {
                v = b_scores[kk]
                  + n0 * W_scores[0 * 32 + kk] + n1 * W_scores[1 * 32 + kk]
                  + n2 * W_scores[2 * 32 + kk] + n3 * W_scores[3 * 32 + kk];
            } else if (kk < 48) {
                v = oya_table[oya[b] * 16 + (kk - 32)];
            } else if (kk < 368) {
                int j = (kk - 48) >> 6;
                int c = (kk - 48) & 63;
                v = dora_table[dora[b * 5 + j] * 64 + c];
            } else {
                int c = kk - 368;
                v = b_hrs[c] + hrs[b * 2 + 0] * W_hrs[0 * 16 + c]
                             + hrs[b * 2 + 1] * W_hrs[1 * 16 + c];
            }
            csh[r * 384 + kk] = v;
        }
    }
    __syncthreads();

    // GEMM: each thread owns one output column c, accumulates 8 rows.
    const int c = blockIdx.x * 128 + tid;
    float acc[8];
#pragma unroll
    for (int r = 0; r < 8; ++r) acc[r] = 0.f;

    const float4* csh4 = reinterpret_cast<const float4*>(csh);  // row stride = 96 float4
#pragma unroll 4
    for (int k4 = 0; k4 < 96; ++k4) {
        float cf[8][4];
#pragma unroll
        for (int r = 0; r < 8; ++r) {
            float4 q = csh4[r * 96 + k4];
            cf[r][0] = q.x; cf[r][1] = q.y; cf[r][2] = q.z; cf[r][3] = q.w;
        }
#pragma unroll
        for (int kk = 0; kk < 4; ++kk) {
            float w = W_info[(k4 * 4 + kk) * Dn + c];
#pragma unroll
            for (int r = 0; r < 8; ++r) acc[r] += cf[r][kk] * w;
        }
    }

    float bi = b_info[c];
#pragma unroll
    for (int r = 0; r < 8; ++r)
        g_table[(INFO_BASE + b0 + r) * Dn + c] = acc[r] + bi;

    if (blockIdx.x == 0) {
        // Sentinel count + rank for this block's 8 rows (ballot/popc; lanes
        // sweep 32 consecutive s per iteration so rank order == s order).
        const int wid  = tid >> 5;
        const int lane = tid & 31;
        const unsigned lmask = (1u << lane) - 1u;
#pragma unroll
        for (int rr = 0; rr < 2; ++rr) {
            const int b = b0 + wid + rr * 4;
            int base = 0;
            for (int it = 0; it < Sn / 32; ++it) {
                int s = it * 32 + lane;
                int a = action[b * Sn + s];
                unsigned bal = __ballot_sync(0xffffffffu, a == 224);
                if (a == 224)
                    g_rank[b * Sn + s] = base + __popc(bal & lmask);
                base += __popc(bal);
            }
            if (lane == 0) g_cnt[b] = base;
        }
    } else {
        // Copy action_table into g_table rows 0..224 (float4, grid-stride).
        const float4* src4 = reinterpret_cast<const float4*>(action_table);
        float4*       dst4 = reinterpret_cast<float4*>(g_table);
        const int nf4    = 225 * (Dn / 4);                 // 28800
        const int nthr   = 3 * 64 * 128;                   // 24576 copy threads
        int lin = ((blockIdx.x - 1) * 64 + blockIdx.y) * 128 + tid;
        for (int i = lin; i < nf4; i += nthr)
            dst4[i] = src4[i];
    }
}

// ---------------------------------------------------------------------------
// Kernel 2: build g_row[b,s]. One block per batch row b. The block computes
// rowoff(b) = sum(g_cnt[0..b-1]) itself (2 KB, L2-hot, block reduce), then
// writes the final table row index for every position (coalesced).
// ---------------------------------------------------------------------------
__global__ __launch_bounds__(128) void kernel_prep(const int* __restrict__ action)
{
    __shared__ int wsh[4];
    const int b = blockIdx.x;
    const int t = threadIdx.x;

    int partial = 0;
    for (int j = t; j < b; j += 128) partial += g_cnt[j];
#pragma unroll
    for (int off = 16; off > 0; off >>= 1)
        partial += __shfl_xor_sync(0xffffffffu, partial, off);
    if ((t & 31) == 0) wsh[t >> 5] = partial;
    __syncthreads();
    const int rowoff = wsh[0] + wsh[1] + wsh[2] + wsh[3];

#pragma unroll
    for (int j = 0; j < 4; ++j) {
        int s  = t + j * 128;
        int bs = b * Sn + s;
        int a  = action[bs];
        int row = a;
        if (a == 224) {
            int occ = rowoff + g_rank[bs];
            occ = occ < (Bn - 1) ? occ : (Bn - 1);
            row = INFO_BASE + occ;
        }
        g_row[bs] = row;
    }
}

// ---------------------------------------------------------------------------
// Kernel 3: pure branch-free gather (the 537 MB write) — same structure that
// measured 75.6us @ DRAM 79.8% in R4: one index load + one table load +
// streaming store, 8 independent float4 per thread.
// ---------------------------------------------------------------------------
#define MAIN_TPB 256
#define MAIN_VPT 8
__global__ __launch_bounds__(MAIN_TPB) void kernel_main(float* __restrict__ out)
{
    const int stride = gridDim.x * MAIN_TPB;           // = n4 / MAIN_VPT
    int idx = blockIdx.x * MAIN_TPB + threadIdx.x;
    const float4* tbl4 = reinterpret_cast<const float4*>(g_table);
    float4*       out4 = reinterpret_cast<float4*>(out);

    int    id[MAIN_VPT];
    float4 v[MAIN_VPT];
#pragma unroll
    for (int i = 0; i < MAIN_VPT; ++i) {
        id[i] = idx + i * stride;
        int bs = id[i] >> 7;          // /128 float4 per (b,s)
        int d4 = id[i] & 127;
        int row = __ldg(&g_row[bs]);
        v[i] = __ldg(&tbl4[row * 128 + d4]);
    }
#pragma unroll
    for (int i = 0; i < MAIN_VPT; ++i)
        __stcs(&out4[id[i]], v[i]);
}

// ---------------------------------------------------------------------------
// Launch
// Input order (metadata): scores, oya, dora, honba_riichi_sticks, action, mask,
//   action_table, oya_table, dora_table, ln_gamma, ln_beta, W_scores, b_scores,
//   W_hrs, b_hrs, W_info, b_info
// ---------------------------------------------------------------------------
extern "C" void kernel_launch(void* const* d_in, const int* in_sizes, int n_in,
                              void* d_out, int out_size)
{
    const float* scores       = (const float*)d_in[0];
    const int*   oya          = (const int*)  d_in[1];
    const int*   dora         = (const int*)  d_in[2];
    const float* hrs          = (const float*)d_in[3];
    const int*   action       = (const int*)  d_in[4];
    /* mask d_in[5] unused */
    const float* action_table = (const float*)d_in[6];
    const float* oya_table    = (const float*)d_in[7];
    const float* dora_table   = (const float*)d_in[8];
    const float* ln_gamma     = (const float*)d_in[9];
    const float* ln_beta      = (const float*)d_in[10];
    const float* W_scores     = (const float*)d_in[11];
    const float* b_scores     = (const float*)d_in[12];
    const float* W_hrs        = (const float*)d_in[13];
    const float* b_hrs        = (const float*)d_in[14];
    const float* W_info       = (const float*)d_in[15];
    const float* b_info       = (const float*)d_in[16];
    float* out = (float*)d_out;

    dim3 gi(Dn / 128, Bn / 8);
    kernel_info<<<gi, 128>>>(scores, oya, dora, hrs, action, action_table,
                             oya_table, dora_table,
                             ln_gamma, ln_beta, W_scores, b_scores,
                             W_hrs, b_hrs, W_info, b_info);

    kernel_prep<<<Bn, 128>>>(action);

    const int n4   = Bn * Sn * (Dn / 4);
    const int grid = n4 / (MAIN_TPB * MAIN_VPT);   // 16384
    kernel_main<<<grid, MAIN_TPB>>>(out);
}